// round 1
// baseline (speedup 1.0000x reference)
#include <cuda_runtime.h>

#define Bb 8
#define Cc 512
#define Ll 4096
#define Dd 64

// Scratch (device globals — no allocation allowed in kernel_launch)
__device__ float g_q[(size_t)Bb * Ll * Dd];   // [B, L, 64]
__device__ float g_k[(size_t)Bb * Dd * Ll];   // [B, 64, L]
__device__ float g_v[(size_t)Bb * Cc * Ll];   // [B, C, L]
__device__ float g_e[(size_t)Bb * Ll * Ll];   // [B, L, L] energy / attn (in-place)

// ---------------------------------------------------------------------------
// Kernel 1: fused q/k projection.
// q[b,l,d] = sum_c x[b,c,l] * Wq[d,c] + bq[d]
// k[b,d,l] = sum_c x[b,c,l] * Wk[d,c] + bk[d]
// grid (L/64, B), block 256 (tx=d 0..63, ty=l-group 0..3, 16 l each)
// ---------------------------------------------------------------------------
__global__ __launch_bounds__(256) void proj_qk_kernel(
    const float* __restrict__ x,
    const float* __restrict__ Wq, const float* __restrict__ bq,
    const float* __restrict__ Wk, const float* __restrict__ bk)
{
    const int b  = blockIdx.y;
    const int l0 = blockIdx.x * 64;

    __shared__ float xs[64][64];    // [c][l]
    __shared__ float wqs[64][65];   // [c][d], padded
    __shared__ float wks[64][65];

    const int t  = threadIdx.x;
    const int tx = t & 63;          // d
    const int ty = t >> 6;          // l-group

    float accq[16], acck[16];
#pragma unroll
    for (int i = 0; i < 16; i++) { accq[i] = 0.f; acck[i] = 0.f; }

    const float* xb  = x + (size_t)b * Cc * Ll;
    const int row    = t >> 2;        // 0..63 (c-row for xs, d-row for W)
    const int off0   = (t & 3) * 16;  // 0,16,32,48

    for (int cc = 0; cc < Cc; cc += 64) {
#pragma unroll
        for (int j = 0; j < 16; j += 4) {
            float4 v = *(const float4*)(xb + (size_t)(cc + row) * Ll + l0 + off0 + j);
            *(float4*)&xs[row][off0 + j] = v;
        }
#pragma unroll
        for (int j = 0; j < 16; j += 4) {
            float4 vq = *(const float4*)(Wq + row * Cc + cc + off0 + j);
            wqs[off0 + j + 0][row] = vq.x;
            wqs[off0 + j + 1][row] = vq.y;
            wqs[off0 + j + 2][row] = vq.z;
            wqs[off0 + j + 3][row] = vq.w;
            float4 vk = *(const float4*)(Wk + row * Cc + cc + off0 + j);
            wks[off0 + j + 0][row] = vk.x;
            wks[off0 + j + 1][row] = vk.y;
            wks[off0 + j + 2][row] = vk.z;
            wks[off0 + j + 3][row] = vk.w;
        }
        __syncthreads();
#pragma unroll 4
        for (int ci = 0; ci < 64; ci++) {
            float wq = wqs[ci][tx];
            float wk = wks[ci][tx];
#pragma unroll
            for (int i = 0; i < 16; i++) {
                float xv = xs[ci][ty * 16 + i];
                accq[i] = fmaf(wq, xv, accq[i]);
                acck[i] = fmaf(wk, xv, acck[i]);
            }
        }
        __syncthreads();
    }

    const float bqv = bq[tx];
    const float bkv = bk[tx];
#pragma unroll
    for (int i = 0; i < 16; i++) {
        int l = l0 + ty * 16 + i;
        g_q[((size_t)b * Ll + l) * Dd + tx] = accq[i] + bqv;
        g_k[((size_t)b * Dd + tx) * Ll + l] = acck[i] + bkv;
    }
}

// ---------------------------------------------------------------------------
// Kernel 2: row softmax on g_e, in place. grid (L, B), block 256.
// ---------------------------------------------------------------------------
__device__ __forceinline__ float warpMax(float v) {
#pragma unroll
    for (int o = 16; o; o >>= 1) v = fmaxf(v, __shfl_xor_sync(0xffffffffu, v, o));
    return v;
}
__device__ __forceinline__ float warpSum(float v) {
#pragma unroll
    for (int o = 16; o; o >>= 1) v += __shfl_xor_sync(0xffffffffu, v, o);
    return v;
}

__global__ __launch_bounds__(256) void softmax_kernel()
{
    float* p = g_e + ((size_t)blockIdx.y * Ll + blockIdx.x) * Ll;
    const int t = threadIdx.x;

    float v[16];
#pragma unroll
    for (int j = 0; j < 16; j += 4)
        *(float4*)&v[j] = *(const float4*)(p + t * 16 + j);

    float mx = v[0];
#pragma unroll
    for (int i = 1; i < 16; i++) mx = fmaxf(mx, v[i]);
    mx = warpMax(mx);

    __shared__ float redm[8];
    __shared__ float reds[8];
    if ((t & 31) == 0) redm[t >> 5] = mx;
    __syncthreads();
    mx = redm[0];
#pragma unroll
    for (int i = 1; i < 8; i++) mx = fmaxf(mx, redm[i]);

    float s = 0.f;
#pragma unroll
    for (int i = 0; i < 16; i++) { v[i] = __expf(v[i] - mx); s += v[i]; }
    s = warpSum(s);
    if ((t & 31) == 0) reds[t >> 5] = s;
    __syncthreads();
    s = 0.f;
#pragma unroll
    for (int i = 0; i < 8; i++) s += reds[i];

    const float inv = 1.f / s;
#pragma unroll
    for (int j = 0; j < 16; j += 4) {
        float4 o;
        o.x = v[j + 0] * inv; o.y = v[j + 1] * inv;
        o.z = v[j + 2] * inv; o.w = v[j + 3] * inv;
        *(float4*)(p + t * 16 + j) = o;
    }
}

// ---------------------------------------------------------------------------
// Generic batched SGEMM: C[M,N] = A[M,K] (row-major) * B
//   TRANS_B == 0 : B is [K,N] row-major
//   TRANS_B == 1 : B is [N,K] row-major (i.e. multiply by B^T)
// EPI: 0 raw, 1 += bias[m], 2 C = gamma*acc + X[m,n]
// Tile 128x128x16, 256 threads, 8x8 micro-tiles.
// Requires M,N % 128 == 0, K % 16 == 0 (true for all uses here).
// ---------------------------------------------------------------------------
template <int TRANS_B, int EPI>
__global__ __launch_bounds__(256) void sgemm_k(
    const float* __restrict__ Aall, const float* __restrict__ Ball,
    float* __restrict__ Call,
    int M, int N, int K,
    long long sA, long long sB, long long sC,
    const float* __restrict__ bias,
    const float* __restrict__ gammaPtr,
    const float* __restrict__ Xall, long long sX)
{
    const int bz = blockIdx.z;
    const float* A = Aall + (long long)bz * sA;
    const float* B = Ball + (long long)bz * sB;
    float* C       = Call + (long long)bz * sC;

    const int m0 = blockIdx.y * 128;
    const int n0 = blockIdx.x * 128;

    __shared__ float As[16][128];
    __shared__ float Bs[16][128];

    const int t  = threadIdx.x;
    const int tx = t & 15;   // n micro
    const int ty = t >> 4;   // m micro

    float acc[8][8];
#pragma unroll
    for (int i = 0; i < 8; i++)
#pragma unroll
        for (int j = 0; j < 8; j++) acc[i][j] = 0.f;

    const int la_m  = t >> 2;          // 0..63
    const int la_k  = (t & 3) * 4;     // 0,4,8,12
    const int lbn_k = t >> 5;          // 0..7
    const int lbn_n = (t & 31) * 4;    // 0..124
    const int lbt_n = t >> 2;          // 0..63
    const int lbt_k = (t & 3) * 4;

    for (int k0 = 0; k0 < K; k0 += 16) {
#pragma unroll
        for (int r = 0; r < 2; r++) {
            int m = la_m + r * 64;
            float4 v = *(const float4*)(A + (long long)(m0 + m) * K + k0 + la_k);
            As[la_k + 0][m] = v.x;
            As[la_k + 1][m] = v.y;
            As[la_k + 2][m] = v.z;
            As[la_k + 3][m] = v.w;
        }
        if (TRANS_B) {
#pragma unroll
            for (int r = 0; r < 2; r++) {
                int n = lbt_n + r * 64;
                float4 v = *(const float4*)(B + (long long)(n0 + n) * K + k0 + lbt_k);
                Bs[lbt_k + 0][n] = v.x;
                Bs[lbt_k + 1][n] = v.y;
                Bs[lbt_k + 2][n] = v.z;
                Bs[lbt_k + 3][n] = v.w;
            }
        } else {
#pragma unroll
            for (int r = 0; r < 2; r++) {
                int k = lbn_k + r * 8;
                float4 v = *(const float4*)(B + (long long)(k0 + k) * N + n0 + lbn_n);
                *(float4*)&Bs[k][lbn_n] = v;
            }
        }
        __syncthreads();
#pragma unroll
        for (int kk = 0; kk < 16; kk++) {
            float a[8], bb[8];
            *(float4*)&a[0]  = *(const float4*)&As[kk][ty * 8];
            *(float4*)&a[4]  = *(const float4*)&As[kk][ty * 8 + 4];
            *(float4*)&bb[0] = *(const float4*)&Bs[kk][tx * 8];
            *(float4*)&bb[4] = *(const float4*)&Bs[kk][tx * 8 + 4];
#pragma unroll
            for (int i = 0; i < 8; i++)
#pragma unroll
                for (int j = 0; j < 8; j++)
                    acc[i][j] = fmaf(a[i], bb[j], acc[i][j]);
        }
        __syncthreads();
    }

    float g = 0.f;
    if (EPI == 2) g = gammaPtr[0];

#pragma unroll
    for (int i = 0; i < 8; i++) {
        int m = m0 + ty * 8 + i;
        float bvv = 0.f;
        if (EPI == 1) bvv = bias[m];
#pragma unroll
        for (int j = 0; j < 8; j += 4) {
            int n = n0 + tx * 8 + j;
            float4 o;
            o.x = acc[i][j + 0]; o.y = acc[i][j + 1];
            o.z = acc[i][j + 2]; o.w = acc[i][j + 3];
            if (EPI == 1) { o.x += bvv; o.y += bvv; o.z += bvv; o.w += bvv; }
            if (EPI == 2) {
                float4 xv = *(const float4*)(Xall + (long long)bz * sX +
                                             (long long)m * N + n);
                o.x = fmaf(g, o.x, xv.x);
                o.y = fmaf(g, o.y, xv.y);
                o.z = fmaf(g, o.z, xv.z);
                o.w = fmaf(g, o.w, xv.w);
            }
            *(float4*)(C + (long long)m * N + n) = o;
        }
    }
}

// ---------------------------------------------------------------------------
extern "C" void kernel_launch(void* const* d_in, const int* in_sizes, int n_in,
                              void* d_out, int out_size)
{
    const float* x     = (const float*)d_in[0];
    const float* Wq    = (const float*)d_in[1];
    const float* bq    = (const float*)d_in[2];
    const float* Wk    = (const float*)d_in[3];
    const float* bk    = (const float*)d_in[4];
    const float* Wv    = (const float*)d_in[5];
    const float* bv    = (const float*)d_in[6];
    const float* gamma = (const float*)d_in[7];
    float* out = (float*)d_out;

    float *q, *k, *v, *e;
    cudaGetSymbolAddress((void**)&q, g_q);
    cudaGetSymbolAddress((void**)&k, g_k);
    cudaGetSymbolAddress((void**)&v, g_v);
    cudaGetSymbolAddress((void**)&e, g_e);

    const long long sX  = (long long)Cc * Ll;   // per-batch x / v / out stride
    const long long sQ  = (long long)Ll * Dd;
    const long long sK  = (long long)Dd * Ll;
    const long long sE  = (long long)Ll * Ll;

    // 1) q/k projections
    proj_qk_kernel<<<dim3(Ll / 64, Bb), 256>>>(x, Wq, bq, Wk, bk);

    // 2) v = Wv @ x[b] + bv   (M=C, N=L, K=C; A shared across batch)
    sgemm_k<0, 1><<<dim3(Ll / 128, Cc / 128, Bb), 256>>>(
        Wv, x, v, Cc, Ll, Cc, 0LL, sX, sX, bv, nullptr, nullptr, 0LL);

    // 3) energy = q[b] @ k[b]   (M=L, N=L, K=64)
    sgemm_k<0, 0><<<dim3(Ll / 128, Ll / 128, Bb), 256>>>(
        q, k, e, Ll, Ll, Dd, sQ, sK, sE, nullptr, nullptr, nullptr, 0LL);

    // 4) softmax rows (in place)
    softmax_kernel<<<dim3(Ll, Bb), 256>>>();

    // 5) out = gamma * (v[b] @ attn[b]^T) + x[b]   (M=C, N=L, K=L, B transposed)
    sgemm_k<1, 2><<<dim3(Ll / 128, Cc / 128, Bb), 256>>>(
        v, e, out, Cc, Ll, Ll, sX, sE, sX, nullptr, gamma, x, sX);
}

// round 3
// speedup vs baseline: 3.8137x; 3.8137x over previous
#include <cuda_runtime.h>
#include <cuda_bf16.h>
#include <cstdint>

#define Bb 8
#define Cc 512
#define Ll 4096
#define Dd 64

// ---------------------------------------------------------------------------
// Scratch (device globals)
// ---------------------------------------------------------------------------
__device__ __nv_bfloat16 g_qa[(size_t)Bb * Ll * 192];   // [B,L,192] = [qhi|qhi|qlo]
__device__ __nv_bfloat16 g_kb[(size_t)Bb * Ll * 192];   // [B,L,192] = [khi|klo|khi]
__device__ __nv_bfloat16 g_xT[(size_t)Bb * Ll * Cc];    // [B,L,C] bf16
__device__ __nv_bfloat16 g_wv[(size_t)Cc * Cc];         // [C,C] bf16
__device__ __nv_bfloat16 g_v [(size_t)Bb * Cc * Ll];    // [B,C,L] bf16
__device__ float         g_e [(size_t)Bb * Ll * Ll];    // [B,L,L] energy fp32
__device__ __nv_bfloat16 g_p [(size_t)Bb * Ll * Ll];    // [B,L,L] attn bf16

// ---------------------------------------------------------------------------
// helpers
// ---------------------------------------------------------------------------
__device__ __forceinline__ uint32_t smem_u32(const void* p) {
    uint32_t a;
    asm("{ .reg .u64 t; cvta.to.shared.u64 t, %1; cvt.u32.u64 %0, t; }"
        : "=r"(a) : "l"(p));
    return a;
}
__device__ __forceinline__ void cp16(void* s, const void* g) {
    asm volatile("cp.async.cg.shared.global [%0], [%1], 16;"
                 :: "r"(smem_u32(s)), "l"(g));
}
__device__ __forceinline__ void ldsm_x4(uint32_t* r, uint32_t addr) {
    asm volatile("ldmatrix.sync.aligned.m8n8.x4.shared.b16 {%0,%1,%2,%3}, [%4];"
                 : "=r"(r[0]), "=r"(r[1]), "=r"(r[2]), "=r"(r[3]) : "r"(addr));
}
__device__ __forceinline__ void mma16816(float* d, const uint32_t* a, const uint32_t* b) {
    asm volatile(
        "mma.sync.aligned.m16n8k16.row.col.f32.bf16.bf16.f32 "
        "{%0,%1,%2,%3}, {%4,%5,%6,%7}, {%8,%9}, {%0,%1,%2,%3};"
        : "+f"(d[0]), "+f"(d[1]), "+f"(d[2]), "+f"(d[3])
        : "r"(a[0]), "r"(a[1]), "r"(a[2]), "r"(a[3]), "r"(b[0]), "r"(b[1]));
}

#define TPAD 40   // smem row stride (elems) for a 32-wide k tile (+16B pad)

// ---------------------------------------------------------------------------
// HMMA bf16 GEMM: D[m][n] = sum_k A[m][k]*B[n][k], both K-major row blocks.
// CTA tile 128x128, k-tile 32, cp.async double buffer, 8 warps (4m x 2n).
// EPI: 0 = store fp32; 1 = +bias[m], store bf16; 2 = gamma*acc + X, store fp32
// ---------------------------------------------------------------------------
template <int EPI>
__global__ __launch_bounds__(256) void hgemm(
    const __nv_bfloat16* __restrict__ Aall,
    const __nv_bfloat16* __restrict__ Ball,
    void* __restrict__ Cout,
    int K, int ldC,
    long long sA, long long sB, long long sC,
    const float* __restrict__ bias,
    const float* __restrict__ gptr,
    const float* __restrict__ Xall, long long sX)
{
    __shared__ __nv_bfloat16 As[2][128][TPAD];
    __shared__ __nv_bfloat16 Bs[2][128][TPAD];

    const int t = threadIdx.x, lane = t & 31, wid = t >> 5;
    const int bz = blockIdx.z;
    const int m0 = blockIdx.y * 128, n0 = blockIdx.x * 128;
    const int wm = wid & 3, wn = wid >> 2;

    const __nv_bfloat16* A = Aall + (size_t)bz * sA + (size_t)m0 * K;
    const __nv_bfloat16* B = Ball + (size_t)bz * sB + (size_t)n0 * K;

    const int lrow = t >> 1;          // 0..127
    const int lcol = (t & 1) * 16;    // 0 or 16

    float acc[2][8][4];
#pragma unroll
    for (int i = 0; i < 2; i++)
#pragma unroll
        for (int j = 0; j < 8; j++)
#pragma unroll
            for (int q = 0; q < 4; q++) acc[i][j][q] = 0.f;

    const size_t rowA = (size_t)lrow * K;
    const size_t rowB = (size_t)lrow * K;

#define LOAD_TILE(buf, k0)                                         \
    do {                                                           \
        cp16(&As[buf][lrow][lcol],     A + rowA + (k0) + lcol);    \
        cp16(&As[buf][lrow][lcol + 8], A + rowA + (k0) + lcol + 8);\
        cp16(&Bs[buf][lrow][lcol],     B + rowB + (k0) + lcol);    \
        cp16(&Bs[buf][lrow][lcol + 8], B + rowB + (k0) + lcol + 8);\
        asm volatile("cp.async.commit_group;");                    \
    } while (0)

    LOAD_TILE(0, 0);
    const int nk = K / 32;

    // ldmatrix lane addressing
    const int a_r = lane % 16;             // row within 16
    const int a_c = (lane / 16) * 8;       // k half
    const int b_r = ((lane / 16) * 8) + (lane & 7);
    const int b_c = ((lane >> 3) & 1) * 8;

    for (int kt = 0; kt < nk; kt++) {
        const int buf = kt & 1;
        if (kt + 1 < nk) {
            LOAD_TILE(buf ^ 1, (kt + 1) * 32);
            asm volatile("cp.async.wait_group 1;");
        } else {
            asm volatile("cp.async.wait_group 0;");
        }
        __syncthreads();

#pragma unroll
        for (int ks = 0; ks < 2; ks++) {
            const int k0 = ks * 16;
            uint32_t af[2][4];
#pragma unroll
            for (int mt = 0; mt < 2; mt++) {
                int r = wm * 32 + mt * 16 + a_r;
                ldsm_x4(af[mt], smem_u32(&As[buf][r][k0 + a_c]));
            }
            uint32_t bf_[4][4];
#pragma unroll
            for (int ng = 0; ng < 4; ng++) {
                int r = wn * 64 + ng * 16 + b_r;
                ldsm_x4(bf_[ng], smem_u32(&Bs[buf][r][k0 + b_c]));
            }
#pragma unroll
            for (int mt = 0; mt < 2; mt++)
#pragma unroll
                for (int nt = 0; nt < 8; nt++)
                    mma16816(acc[mt][nt], af[mt], &bf_[nt >> 1][(nt & 1) * 2]);
        }
        __syncthreads();
    }

    // ---------------- epilogue ----------------
    const int cr = lane >> 2;        // 0..7
    const int cc = (lane & 3) * 2;

    if (EPI == 0) {
        float* C = (float*)Cout + (size_t)bz * sC;
#pragma unroll
        for (int mt = 0; mt < 2; mt++)
#pragma unroll
            for (int nt = 0; nt < 8; nt++) {
                int col = n0 + wn * 64 + nt * 8 + cc;
#pragma unroll
                for (int h = 0; h < 2; h++) {
                    int row = m0 + wm * 32 + mt * 16 + cr + h * 8;
                    float2 o = {acc[mt][nt][h * 2], acc[mt][nt][h * 2 + 1]};
                    *(float2*)(C + (size_t)row * ldC + col) = o;
                }
            }
    } else if (EPI == 1) {
        __nv_bfloat16* C = (__nv_bfloat16*)Cout + (size_t)bz * sC;
#pragma unroll
        for (int mt = 0; mt < 2; mt++) {
            float bv0 = bias[m0 + wm * 32 + mt * 16 + cr];
            float bv1 = bias[m0 + wm * 32 + mt * 16 + cr + 8];
#pragma unroll
            for (int nt = 0; nt < 8; nt++) {
                int col = n0 + wn * 64 + nt * 8 + cc;
#pragma unroll
                for (int h = 0; h < 2; h++) {
                    int row = m0 + wm * 32 + mt * 16 + cr + h * 8;
                    float bv = h ? bv1 : bv0;
                    __nv_bfloat162 o;
                    o.x = __float2bfloat16(acc[mt][nt][h * 2] + bv);
                    o.y = __float2bfloat16(acc[mt][nt][h * 2 + 1] + bv);
                    *(__nv_bfloat162*)(C + (size_t)row * ldC + col) = o;
                }
            }
        }
    } else {
        const float g = gptr[0];
        const float* X = Xall + (size_t)bz * sX;
        float* C = (float*)Cout + (size_t)bz * sC;
#pragma unroll
        for (int mt = 0; mt < 2; mt++)
#pragma unroll
            for (int nt = 0; nt < 8; nt++) {
                int col = n0 + wn * 64 + nt * 8 + cc;
#pragma unroll
                for (int h = 0; h < 2; h++) {
                    int row = m0 + wm * 32 + mt * 16 + cr + h * 8;
                    float2 xv = *(const float2*)(X + (size_t)row * ldC + col);
                    float2 o;
                    o.x = fmaf(g, acc[mt][nt][h * 2], xv.x);
                    o.y = fmaf(g, acc[mt][nt][h * 2 + 1], xv.y);
                    *(float2*)(C + (size_t)row * ldC + col) = o;
                }
            }
    }
#undef LOAD_TILE
}

// ---------------------------------------------------------------------------
// q/k projection -> split bf16 layouts  (fp32 math)
// qa[l] = [qhi|qhi|qlo], kb[l] = [khi|klo|khi]  (K=192 energy GEMM ~fp32-exact)
// ---------------------------------------------------------------------------
__global__ __launch_bounds__(256) void proj_qk_kernel(
    const float* __restrict__ x,
    const float* __restrict__ Wq, const float* __restrict__ bq,
    const float* __restrict__ Wk, const float* __restrict__ bk)
{
    const int b  = blockIdx.y;
    const int l0 = blockIdx.x * 64;

    __shared__ float xs[64][64];
    __shared__ float wqs[64][65];
    __shared__ float wks[64][65];

    const int t  = threadIdx.x;
    const int tx = t & 63;
    const int ty = t >> 6;

    float accq[16], acck[16];
#pragma unroll
    for (int i = 0; i < 16; i++) { accq[i] = 0.f; acck[i] = 0.f; }

    const float* xb = x + (size_t)b * Cc * Ll;
    const int row  = t >> 2;
    const int off0 = (t & 3) * 16;

    for (int cc = 0; cc < Cc; cc += 64) {
#pragma unroll
        for (int j = 0; j < 16; j += 4) {
            float4 v = *(const float4*)(xb + (size_t)(cc + row) * Ll + l0 + off0 + j);
            *(float4*)&xs[row][off0 + j] = v;
        }
#pragma unroll
        for (int j = 0; j < 16; j += 4) {
            float4 vq = *(const float4*)(Wq + row * Cc + cc + off0 + j);
            wqs[off0 + j + 0][row] = vq.x;
            wqs[off0 + j + 1][row] = vq.y;
            wqs[off0 + j + 2][row] = vq.z;
            wqs[off0 + j + 3][row] = vq.w;
            float4 vk = *(const float4*)(Wk + row * Cc + cc + off0 + j);
            wks[off0 + j + 0][row] = vk.x;
            wks[off0 + j + 1][row] = vk.y;
            wks[off0 + j + 2][row] = vk.z;
            wks[off0 + j + 3][row] = vk.w;
        }
        __syncthreads();
#pragma unroll 4
        for (int ci = 0; ci < 64; ci++) {
            float wq = wqs[ci][tx];
            float wk = wks[ci][tx];
#pragma unroll
            for (int i = 0; i < 16; i++) {
                float xv = xs[ci][ty * 16 + i];
                accq[i] = fmaf(wq, xv, accq[i]);
                acck[i] = fmaf(wk, xv, acck[i]);
            }
        }
        __syncthreads();
    }

    const float bqv = bq[tx];
    const float bkv = bk[tx];
#pragma unroll
    for (int i = 0; i < 16; i++) {
        int l = l0 + ty * 16 + i;
        size_t base = ((size_t)b * Ll + l) * 192;
        float qv = accq[i] + bqv;
        __nv_bfloat16 qh = __float2bfloat16(qv);
        __nv_bfloat16 ql = __float2bfloat16(qv - __bfloat162float(qh));
        g_qa[base + tx]       = qh;
        g_qa[base + 64 + tx]  = qh;
        g_qa[base + 128 + tx] = ql;
        float kv = acck[i] + bkv;
        __nv_bfloat16 kh = __float2bfloat16(kv);
        __nv_bfloat16 kl = __float2bfloat16(kv - __bfloat162float(kh));
        g_kb[base + tx]       = kh;
        g_kb[base + 64 + tx]  = kl;
        g_kb[base + 128 + tx] = kh;
    }
}

// ---------------------------------------------------------------------------
// x transpose -> bf16 xT[b][l][c]
// ---------------------------------------------------------------------------
__global__ __launch_bounds__(256) void transpose_x_kernel(const float* __restrict__ x)
{
    __shared__ float tile[32][33];
    const int b  = blockIdx.z;
    const int c0 = blockIdx.y * 32;
    const int l0 = blockIdx.x * 32;
    const int tx = threadIdx.x, ty = threadIdx.y;

    const float* xb = x + ((size_t)b * Cc + c0) * Ll + l0;
#pragma unroll
    for (int r = 0; r < 4; r++)
        tile[ty + r * 8][tx] = xb[(size_t)(ty + r * 8) * Ll + tx];
    __syncthreads();

    __nv_bfloat16* o = g_xT + (size_t)b * Ll * Cc;
#pragma unroll
    for (int r = 0; r < 4; r++) {
        int l = l0 + ty + r * 8;
        o[(size_t)l * Cc + c0 + tx] = __float2bfloat16(tile[tx][ty + r * 8]);
    }
}

__global__ __launch_bounds__(256) void conv_wv_kernel(const float* __restrict__ Wv)
{
    int idx = blockIdx.x * 256 + threadIdx.x;
    g_wv[idx] = __float2bfloat16(Wv[idx]);
}

// ---------------------------------------------------------------------------
// Row softmax: fp32 energy -> bf16 attn
// ---------------------------------------------------------------------------
__device__ __forceinline__ float warpMax(float v) {
#pragma unroll
    for (int o = 16; o; o >>= 1) v = fmaxf(v, __shfl_xor_sync(0xffffffffu, v, o));
    return v;
}
__device__ __forceinline__ float warpSum(float v) {
#pragma unroll
    for (int o = 16; o; o >>= 1) v += __shfl_xor_sync(0xffffffffu, v, o);
    return v;
}

__global__ __launch_bounds__(256) void softmax_kernel()
{
    const size_t roff = ((size_t)blockIdx.y * Ll + blockIdx.x) * Ll;
    const float* p = g_e + roff;
    __nv_bfloat16* po = g_p + roff;
    const int t = threadIdx.x;

    float v[16];
#pragma unroll
    for (int j = 0; j < 16; j += 4)
        *(float4*)&v[j] = *(const float4*)(p + t * 16 + j);

    float mx = v[0];
#pragma unroll
    for (int i = 1; i < 16; i++) mx = fmaxf(mx, v[i]);
    mx = warpMax(mx);

    __shared__ float redm[8];
    __shared__ float reds[8];
    if ((t & 31) == 0) redm[t >> 5] = mx;
    __syncthreads();
    mx = redm[0];
#pragma unroll
    for (int i = 1; i < 8; i++) mx = fmaxf(mx, redm[i]);

    float s = 0.f;
#pragma unroll
    for (int i = 0; i < 16; i++) { v[i] = __expf(v[i] - mx); s += v[i]; }
    s = warpSum(s);
    if ((t & 31) == 0) reds[t >> 5] = s;
    __syncthreads();
    s = 0.f;
#pragma unroll
    for (int i = 0; i < 8; i++) s += reds[i];

    const float inv = 1.f / s;
    __align__(16) __nv_bfloat16 ob[16];
#pragma unroll
    for (int i = 0; i < 16; i++) ob[i] = __float2bfloat16(v[i] * inv);
    *(uint4*)(po + t * 16)     = *(const uint4*)&ob[0];
    *(uint4*)(po + t * 16 + 8) = *(const uint4*)&ob[8];
}

// ---------------------------------------------------------------------------
extern "C" void kernel_launch(void* const* d_in, const int* in_sizes, int n_in,
                              void* d_out, int out_size)
{
    const float* x     = (const float*)d_in[0];
    const float* Wq    = (const float*)d_in[1];
    const float* bq    = (const float*)d_in[2];
    const float* Wk    = (const float*)d_in[3];
    const float* bk    = (const float*)d_in[4];
    const float* Wv    = (const float*)d_in[5];
    const float* bv    = (const float*)d_in[6];
    const float* gamma = (const float*)d_in[7];
    float* out = (float*)d_out;

    __nv_bfloat16 *qa, *kb, *xT, *wv, *v, *p;
    float *e;
    cudaGetSymbolAddress((void**)&qa, g_qa);
    cudaGetSymbolAddress((void**)&kb, g_kb);
    cudaGetSymbolAddress((void**)&xT, g_xT);
    cudaGetSymbolAddress((void**)&wv, g_wv);
    cudaGetSymbolAddress((void**)&v,  g_v);
    cudaGetSymbolAddress((void**)&e,  g_e);
    cudaGetSymbolAddress((void**)&p,  g_p);

    // 1) prologue conversions
    proj_qk_kernel<<<dim3(Ll / 64, Bb), 256>>>(x, Wq, bq, Wk, bk);
    transpose_x_kernel<<<dim3(Ll / 32, Cc / 32, Bb), dim3(32, 8)>>>(x);
    conv_wv_kernel<<<(Cc * Cc) / 256, 256>>>(Wv);

    // 2) v = Wv @ x + bv  -> bf16 [C, L]
    hgemm<1><<<dim3(Ll / 128, Cc / 128, Bb), 256>>>(
        wv, xT, v, Cc, Ll,
        0LL, (long long)Ll * Cc, (long long)Cc * Ll,
        bv, nullptr, nullptr, 0LL);

    // 3) energy = q @ k^T  (K=192 split) -> fp32 [L, L]
    hgemm<0><<<dim3(Ll / 128, Ll / 128, Bb), 256>>>(
        qa, kb, e, 192, Ll,
        (long long)Ll * 192, (long long)Ll * 192, (long long)Ll * Ll,
        nullptr, nullptr, nullptr, 0LL);

    // 4) softmax rows -> bf16 attn
    softmax_kernel<<<dim3(Ll, Bb), 256>>>();

    // 5) out = gamma * (v @ attn^T) + x  -> fp32 [C, L]
    hgemm<2><<<dim3(Ll / 128, Cc / 128, Bb), 256>>>(
        v, p, out, Ll, Ll,
        (long long)Cc * Ll, (long long)Ll * Ll, (long long)Cc * Ll,
        nullptr, gamma, x, (long long)Cc * Ll);
}

// round 4
// speedup vs baseline: 4.5460x; 1.1920x over previous
#include <cuda_runtime.h>
#include <cuda_bf16.h>
#include <cstdint>

#define Bb 8
#define Cc 512
#define Ll 4096
#define Dd 64

// ---------------------------------------------------------------------------
// Scratch (device globals)
// ---------------------------------------------------------------------------
__device__ __nv_bfloat16 g_qa[(size_t)Bb * Ll * 192];   // [B,L,192] = [qhi|qhi|qlo]
__device__ __nv_bfloat16 g_kb[(size_t)Bb * Ll * 192];   // [B,L,192] = [khi|klo|khi]
__device__ __nv_bfloat16 g_xT[(size_t)Bb * Ll * Cc];    // [B,L,C] bf16
__device__ __nv_bfloat16 g_wv[(size_t)Cc * Cc];         // [C,C] bf16
__device__ __nv_bfloat16 g_v [(size_t)Bb * Cc * Ll];    // [B,C,L] bf16
__device__ __nv_bfloat16 g_p [(size_t)Bb * Ll * Ll];    // [B,L,L] exp(energy) bf16
__device__ float g_spart[(size_t)Bb * 32 * Ll];         // [B,jtile,L] row-sum partials
__device__ float g_invs [(size_t)Bb * Ll];              // [B,L] 1/rowsum

// ---------------------------------------------------------------------------
// helpers
// ---------------------------------------------------------------------------
__device__ __forceinline__ uint32_t smem_u32(const void* p) {
    uint32_t a;
    asm("{ .reg .u64 t; cvta.to.shared.u64 t, %1; cvt.u32.u64 %0, t; }"
        : "=r"(a) : "l"(p));
    return a;
}
__device__ __forceinline__ void cp16u(uint32_t s, const void* g) {
    asm volatile("cp.async.cg.shared.global [%0], [%1], 16;" :: "r"(s), "l"(g));
}
__device__ __forceinline__ void ldsm_x4(uint32_t* r, uint32_t addr) {
    asm volatile("ldmatrix.sync.aligned.m8n8.x4.shared.b16 {%0,%1,%2,%3}, [%4];"
                 : "=r"(r[0]), "=r"(r[1]), "=r"(r[2]), "=r"(r[3]) : "r"(addr));
}
__device__ __forceinline__ void mma16816(float* d, const uint32_t* a, const uint32_t* b) {
    asm volatile(
        "mma.sync.aligned.m16n8k16.row.col.f32.bf16.bf16.f32 "
        "{%0,%1,%2,%3}, {%4,%5,%6,%7}, {%8,%9}, {%0,%1,%2,%3};"
        : "+f"(d[0]), "+f"(d[1]), "+f"(d[2]), "+f"(d[3])
        : "r"(a[0]), "r"(a[1]), "r"(a[2]), "r"(a[3]), "r"(b[0]), "r"(b[1]));
}

// dynamic smem: A[2] 16KB each @0, B[2] 16KB each @32768, s_part 1KB @65536
static constexpr int SMEM_SZ = 65536 + 1024;

// ---------------------------------------------------------------------------
// HMMA bf16 GEMM: D[m][n] = sum_k A[m][k]*B[n][k] (both K-major).
// CTA 128x128, k-tile 64, XOR-swizzled smem, cp.async double buffer,
// 8 warps (4m x 2n), warptile 32x64.
// EPI: 1 = +bias[m], store bf16
//      2 = (gamma*invS[n])*acc + X[m][n], store fp32
//      3 = exp(acc) -> bf16 store; per-CTA row sums -> spart
// ---------------------------------------------------------------------------
template <int EPI>
__global__ __launch_bounds__(256) void hgemm(
    const __nv_bfloat16* __restrict__ Aall,
    const __nv_bfloat16* __restrict__ Ball,
    void* __restrict__ Cout,
    int K, int ldC,
    long long sA, long long sB, long long sC,
    const float* __restrict__ bias,
    const float* __restrict__ gptr,
    const float* __restrict__ Xall, long long sX,
    float* __restrict__ spart,
    const float* __restrict__ invS)
{
    extern __shared__ __align__(1024) char sm[];
    const uint32_t smA = smem_u32(sm);
    const uint32_t smB = smA + 32768;
    float* s_part = (float*)(sm + 65536);

    const int t = threadIdx.x, lane = t & 31, wid = t >> 5;
    const int bz = blockIdx.z;
    const int m0 = blockIdx.y * 128, n0 = blockIdx.x * 128;
    const int wm = wid & 3, wn = wid >> 2;

    const __nv_bfloat16* A = Aall + (size_t)bz * sA + (size_t)m0 * K;
    const __nv_bfloat16* B = Ball + (size_t)bz * sB + (size_t)n0 * K;

    // loader: thread t -> row t>>1, chunks (t&1)*4 .. +3 (16B each, 8 bf16)
    const int lrow = t >> 1;
    const int lc0  = (t & 1) * 4;
    const int lswz = lrow & 7;
    const __nv_bfloat16* Ar = A + (size_t)lrow * K;
    const __nv_bfloat16* Br = B + (size_t)lrow * K;
    const uint32_t dA0 = smA + lrow * 128;
    const uint32_t dB0 = smB + lrow * 128;

    float acc[2][8][4];
#pragma unroll
    for (int i = 0; i < 2; i++)
#pragma unroll
        for (int j = 0; j < 8; j++)
#pragma unroll
            for (int q = 0; q < 4; q++) acc[i][j][q] = 0.f;

#define LOAD_TILE(stg, k0)                                                   \
    do {                                                                     \
        _Pragma("unroll")                                                    \
        for (int j = 0; j < 4; j++) {                                        \
            int c = lc0 + j;                                                 \
            uint32_t ph = (uint32_t)((c ^ lswz) << 4);                       \
            cp16u(dA0 + (stg) * 16384 + ph, Ar + (k0) + c * 8);              \
            cp16u(dB0 + (stg) * 16384 + ph, Br + (k0) + c * 8);              \
        }                                                                    \
        asm volatile("cp.async.commit_group;");                              \
    } while (0)

    LOAD_TILE(0, 0);
    const int nk = K / 64;

    const int a_r = lane & 15;
    const int a_ch = lane >> 4;         // 0/1
    const int b_r = ((lane >> 4) << 3) + (lane & 7);
    const int b_ch = (lane >> 3) & 1;   // 0/1

    for (int kt = 0; kt < nk; kt++) {
        const int buf = kt & 1;
        if (kt + 1 < nk) {
            LOAD_TILE(buf ^ 1, (kt + 1) * 64);
            asm volatile("cp.async.wait_group 1;");
        } else {
            asm volatile("cp.async.wait_group 0;");
        }
        __syncthreads();

        const uint32_t bA = smA + buf * 16384;
        const uint32_t bB = smB + buf * 16384;
#pragma unroll
        for (int s = 0; s < 4; s++) {
            uint32_t af[2][4];
#pragma unroll
            for (int mt = 0; mt < 2; mt++) {
                int r = wm * 32 + mt * 16 + a_r;
                int c = s * 2 + a_ch;
                ldsm_x4(af[mt], bA + r * 128 + ((c ^ (r & 7)) << 4));
            }
            uint32_t bf_[4][4];
#pragma unroll
            for (int ng = 0; ng < 4; ng++) {
                int r = wn * 64 + ng * 16 + b_r;
                int c = s * 2 + b_ch;
                ldsm_x4(bf_[ng], bB + r * 128 + ((c ^ (r & 7)) << 4));
            }
#pragma unroll
            for (int mt = 0; mt < 2; mt++)
#pragma unroll
                for (int nt = 0; nt < 8; nt++)
                    mma16816(acc[mt][nt], af[mt], &bf_[nt >> 1][(nt & 1) * 2]);
        }
        __syncthreads();
    }
#undef LOAD_TILE

    // ---------------- epilogue ----------------
    const int cr = lane >> 2;
    const int cc = (lane & 3) * 2;

    if (EPI == 1) {
        __nv_bfloat16* C = (__nv_bfloat16*)Cout + (size_t)bz * sC;
#pragma unroll
        for (int mt = 0; mt < 2; mt++) {
            float bv0 = bias[m0 + wm * 32 + mt * 16 + cr];
            float bv1 = bias[m0 + wm * 32 + mt * 16 + cr + 8];
#pragma unroll
            for (int nt = 0; nt < 8; nt++) {
                int col = n0 + wn * 64 + nt * 8 + cc;
#pragma unroll
                for (int h = 0; h < 2; h++) {
                    int row = m0 + wm * 32 + mt * 16 + cr + h * 8;
                    float bv = h ? bv1 : bv0;
                    __nv_bfloat162 o;
                    o.x = __float2bfloat16(acc[mt][nt][h * 2] + bv);
                    o.y = __float2bfloat16(acc[mt][nt][h * 2 + 1] + bv);
                    *(__nv_bfloat162*)(C + (size_t)row * ldC + col) = o;
                }
            }
        }
    } else if (EPI == 2) {
        const float g = gptr[0];
        const float* X = Xall + (size_t)bz * sX;
        const float* iS = invS + (size_t)bz * Ll;
        float* C = (float*)Cout + (size_t)bz * sC;
#pragma unroll
        for (int nt = 0; nt < 8; nt++) {
            int col = n0 + wn * 64 + nt * 8 + cc;
            float gi0 = g * iS[col];
            float gi1 = g * iS[col + 1];
#pragma unroll
            for (int mt = 0; mt < 2; mt++)
#pragma unroll
                for (int h = 0; h < 2; h++) {
                    int row = m0 + wm * 32 + mt * 16 + cr + h * 8;
                    float2 xv = *(const float2*)(X + (size_t)row * ldC + col);
                    float2 o;
                    o.x = fmaf(gi0, acc[mt][nt][h * 2], xv.x);
                    o.y = fmaf(gi1, acc[mt][nt][h * 2 + 1], xv.y);
                    *(float2*)(C + (size_t)row * ldC + col) = o;
                }
        }
    } else {
        // EPI 3: exp + bf16 store + row-sum partials
        __nv_bfloat16* C = (__nv_bfloat16*)Cout + (size_t)bz * sC;
        float rs[2][2] = {{0.f, 0.f}, {0.f, 0.f}};
#pragma unroll
        for (int mt = 0; mt < 2; mt++)
#pragma unroll
            for (int nt = 0; nt < 8; nt++) {
                int col = n0 + wn * 64 + nt * 8 + cc;
#pragma unroll
                for (int h = 0; h < 2; h++) {
                    int row = m0 + wm * 32 + mt * 16 + cr + h * 8;
                    float e0 = __expf(acc[mt][nt][h * 2]);
                    float e1 = __expf(acc[mt][nt][h * 2 + 1]);
                    __nv_bfloat162 o;
                    o.x = __float2bfloat16(e0);
                    o.y = __float2bfloat16(e1);
                    *(__nv_bfloat162*)(C + (size_t)row * ldC + col) = o;
                    rs[mt][h] += e0 + e1;
                }
            }
        // quad reduce (lanes sharing cr)
#pragma unroll
        for (int mt = 0; mt < 2; mt++)
#pragma unroll
            for (int h = 0; h < 2; h++) {
                float v = rs[mt][h];
                v += __shfl_xor_sync(0xffffffffu, v, 1);
                v += __shfl_xor_sync(0xffffffffu, v, 2);
                rs[mt][h] = v;
            }
        if ((lane & 3) == 0) {
#pragma unroll
            for (int mt = 0; mt < 2; mt++)
#pragma unroll
                for (int h = 0; h < 2; h++)
                    s_part[wn * 128 + wm * 32 + mt * 16 + cr + h * 8] = rs[mt][h];
        }
        __syncthreads();
        if (t < 128) {
            size_t idx = ((size_t)bz * 32 + blockIdx.x) * Ll + m0 + t;
            spart[idx] = s_part[t] + s_part[128 + t];
        }
    }
}

// ---------------------------------------------------------------------------
// reduce partials -> 1/rowsum
// ---------------------------------------------------------------------------
__global__ __launch_bounds__(256) void reduce_s_kernel()
{
    int idx = blockIdx.x * 256 + threadIdx.x;     // 0 .. B*L-1
    int b = idx >> 12, m = idx & 4095;
    float s = 0.f;
#pragma unroll 8
    for (int nt = 0; nt < 32; nt++)
        s += g_spart[((size_t)b * 32 + nt) * Ll + m];
    g_invs[idx] = 1.0f / s;
}

// ---------------------------------------------------------------------------
// q/k projection -> split bf16 layouts (fp32 math)
// ---------------------------------------------------------------------------
__global__ __launch_bounds__(256) void proj_qk_kernel(
    const float* __restrict__ x,
    const float* __restrict__ Wq, const float* __restrict__ bq,
    const float* __restrict__ Wk, const float* __restrict__ bk)
{
    const int b  = blockIdx.y;
    const int l0 = blockIdx.x * 64;

    __shared__ float xs[64][64];
    __shared__ float wqs[64][65];
    __shared__ float wks[64][65];

    const int t  = threadIdx.x;
    const int tx = t & 63;
    const int ty = t >> 6;

    float accq[16], acck[16];
#pragma unroll
    for (int i = 0; i < 16; i++) { accq[i] = 0.f; acck[i] = 0.f; }

    const float* xb = x + (size_t)b * Cc * Ll;
    const int row  = t >> 2;
    const int off0 = (t & 3) * 16;

    for (int cc = 0; cc < Cc; cc += 64) {
#pragma unroll
        for (int j = 0; j < 16; j += 4) {
            float4 v = *(const float4*)(xb + (size_t)(cc + row) * Ll + l0 + off0 + j);
            *(float4*)&xs[row][off0 + j] = v;
        }
#pragma unroll
        for (int j = 0; j < 16; j += 4) {
            float4 vq = *(const float4*)(Wq + row * Cc + cc + off0 + j);
            wqs[off0 + j + 0][row] = vq.x;
            wqs[off0 + j + 1][row] = vq.y;
            wqs[off0 + j + 2][row] = vq.z;
            wqs[off0 + j + 3][row] = vq.w;
            float4 vk = *(const float4*)(Wk + row * Cc + cc + off0 + j);
            wks[off0 + j + 0][row] = vk.x;
            wks[off0 + j + 1][row] = vk.y;
            wks[off0 + j + 2][row] = vk.z;
            wks[off0 + j + 3][row] = vk.w;
        }
        __syncthreads();
#pragma unroll 4
        for (int ci = 0; ci < 64; ci++) {
            float wq = wqs[ci][tx];
            float wk = wks[ci][tx];
#pragma unroll
            for (int i = 0; i < 16; i++) {
                float xv = xs[ci][ty * 16 + i];
                accq[i] = fmaf(wq, xv, accq[i]);
                acck[i] = fmaf(wk, xv, acck[i]);
            }
        }
        __syncthreads();
    }

    const float bqv = bq[tx];
    const float bkv = bk[tx];
#pragma unroll
    for (int i = 0; i < 16; i++) {
        int l = l0 + ty * 16 + i;
        size_t base = ((size_t)b * Ll + l) * 192;
        float qv = accq[i] + bqv;
        __nv_bfloat16 qh = __float2bfloat16(qv);
        __nv_bfloat16 ql = __float2bfloat16(qv - __bfloat162float(qh));
        g_qa[base + tx]       = qh;
        g_qa[base + 64 + tx]  = qh;
        g_qa[base + 128 + tx] = ql;
        float kv = acck[i] + bkv;
        __nv_bfloat16 kh = __float2bfloat16(kv);
        __nv_bfloat16 kl = __float2bfloat16(kv - __bfloat162float(kh));
        g_kb[base + tx]       = kh;
        g_kb[base + 64 + tx]  = kl;
        g_kb[base + 128 + tx] = kh;
    }
}

// ---------------------------------------------------------------------------
__global__ __launch_bounds__(256) void transpose_x_kernel(const float* __restrict__ x)
{
    __shared__ float tile[32][33];
    const int b  = blockIdx.z;
    const int c0 = blockIdx.y * 32;
    const int l0 = blockIdx.x * 32;
    const int tx = threadIdx.x, ty = threadIdx.y;

    const float* xb = x + ((size_t)b * Cc + c0) * Ll + l0;
#pragma unroll
    for (int r = 0; r < 4; r++)
        tile[ty + r * 8][tx] = xb[(size_t)(ty + r * 8) * Ll + tx];
    __syncthreads();

    __nv_bfloat16* o = g_xT + (size_t)b * Ll * Cc;
#pragma unroll
    for (int r = 0; r < 4; r++) {
        int l = l0 + ty + r * 8;
        o[(size_t)l * Cc + c0 + tx] = __float2bfloat16(tile[tx][ty + r * 8]);
    }
}

__global__ __launch_bounds__(256) void conv_wv_kernel(const float* __restrict__ Wv)
{
    int idx = blockIdx.x * 256 + threadIdx.x;
    g_wv[idx] = __float2bfloat16(Wv[idx]);
}

// ---------------------------------------------------------------------------
extern "C" void kernel_launch(void* const* d_in, const int* in_sizes, int n_in,
                              void* d_out, int out_size)
{
    const float* x     = (const float*)d_in[0];
    const float* Wq    = (const float*)d_in[1];
    const float* bq    = (const float*)d_in[2];
    const float* Wk    = (const float*)d_in[3];
    const float* bk    = (const float*)d_in[4];
    const float* Wv    = (const float*)d_in[5];
    const float* bv    = (const float*)d_in[6];
    const float* gamma = (const float*)d_in[7];
    float* out = (float*)d_out;

    __nv_bfloat16 *qa, *kb, *xT, *wv, *v, *p;
    float *spart, *invs;
    cudaGetSymbolAddress((void**)&qa, g_qa);
    cudaGetSymbolAddress((void**)&kb, g_kb);
    cudaGetSymbolAddress((void**)&xT, g_xT);
    cudaGetSymbolAddress((void**)&wv, g_wv);
    cudaGetSymbolAddress((void**)&v,  g_v);
    cudaGetSymbolAddress((void**)&p,  g_p);
    cudaGetSymbolAddress((void**)&spart, g_spart);
    cudaGetSymbolAddress((void**)&invs,  g_invs);

    cudaFuncSetAttribute(hgemm<1>, cudaFuncAttributeMaxDynamicSharedMemorySize, SMEM_SZ);
    cudaFuncSetAttribute(hgemm<2>, cudaFuncAttributeMaxDynamicSharedMemorySize, SMEM_SZ);
    cudaFuncSetAttribute(hgemm<3>, cudaFuncAttributeMaxDynamicSharedMemorySize, SMEM_SZ);

    // 1) prologue conversions
    proj_qk_kernel<<<dim3(Ll / 64, Bb), 256>>>(x, Wq, bq, Wk, bk);
    transpose_x_kernel<<<dim3(Ll / 32, Cc / 32, Bb), dim3(32, 8)>>>(x);
    conv_wv_kernel<<<(Cc * Cc) / 256, 256>>>(Wv);

    // 2) v = Wv @ x + bv  -> bf16 [C, L]
    hgemm<1><<<dim3(Ll / 128, Cc / 128, Bb), 256, SMEM_SZ>>>(
        wv, xT, v, Cc, Ll,
        0LL, (long long)Ll * Cc, (long long)Cc * Ll,
        bv, nullptr, nullptr, 0LL, nullptr, nullptr);

    // 3) p = exp(q @ k^T)  (K=192 split) -> bf16 [L, L] + row-sum partials
    hgemm<3><<<dim3(Ll / 128, Ll / 128, Bb), 256, SMEM_SZ>>>(
        qa, kb, p, 192, Ll,
        (long long)Ll * 192, (long long)Ll * 192, (long long)Ll * Ll,
        nullptr, nullptr, nullptr, 0LL, spart, nullptr);

    // 4) invS = 1 / rowsum
    reduce_s_kernel<<<(Bb * Ll) / 256, 256>>>();

    // 5) out = (gamma*invS[i]) * (v @ p^T) + x  -> fp32 [C, L]
    hgemm<2><<<dim3(Ll / 128, Cc / 128, Bb), 256, SMEM_SZ>>>(
        v, p, out, Ll, Ll,
        (long long)Cc * Ll, (long long)Ll * Ll, (long long)Cc * Ll,
        nullptr, gamma, x, (long long)Cc * Ll, nullptr, invs);
}

// round 5
// speedup vs baseline: 4.6486x; 1.0226x over previous
#include <cuda_runtime.h>
#include <cuda_bf16.h>
#include <cstdint>

#define Bb 8
#define Cc 512
#define Ll 4096
#define Dd 64

// ---------------------------------------------------------------------------
// Scratch (device globals)
// ---------------------------------------------------------------------------
__device__ __nv_bfloat16 g_qa[(size_t)Bb * Ll * 192];   // [B,L,192] = [qhi|qhi|qlo]
__device__ __nv_bfloat16 g_kb[(size_t)Bb * Ll * 192];   // [B,L,192] = [khi|klo|khi]
__device__ __nv_bfloat16 g_xT[(size_t)Bb * Ll * Cc];    // [B,L,C] bf16
__device__ __nv_bfloat16 g_wv[(size_t)Cc * Cc];         // [C,C] bf16
__device__ __nv_bfloat16 g_v [(size_t)Bb * Cc * Ll];    // [B,C,L] bf16
__device__ __nv_bfloat16 g_p [(size_t)Bb * Ll * Ll];    // [B,L,L] exp(energy) bf16
__device__ float g_spart[(size_t)Bb * 32 * Ll];         // [B,jtile,L] row-sum partials
__device__ float g_invs [(size_t)Bb * Ll];              // [B,L] 1/rowsum

// ---------------------------------------------------------------------------
// helpers
// ---------------------------------------------------------------------------
__device__ __forceinline__ uint32_t smem_u32(const void* p) {
    uint32_t a;
    asm("{ .reg .u64 t; cvta.to.shared.u64 t, %1; cvt.u32.u64 %0, t; }"
        : "=r"(a) : "l"(p));
    return a;
}
__device__ __forceinline__ void cp16u(uint32_t s, const void* g) {
    asm volatile("cp.async.cg.shared.global [%0], [%1], 16;" :: "r"(s), "l"(g));
}
__device__ __forceinline__ void ldsm_x4(uint32_t* r, uint32_t addr) {
    asm volatile("ldmatrix.sync.aligned.m8n8.x4.shared.b16 {%0,%1,%2,%3}, [%4];"
                 : "=r"(r[0]), "=r"(r[1]), "=r"(r[2]), "=r"(r[3]) : "r"(addr));
}
__device__ __forceinline__ void mma16816(float* d, const uint32_t* a, const uint32_t* b) {
    asm volatile(
        "mma.sync.aligned.m16n8k16.row.col.f32.bf16.bf16.f32 "
        "{%0,%1,%2,%3}, {%4,%5,%6,%7}, {%8,%9}, {%0,%1,%2,%3};"
        : "+f"(d[0]), "+f"(d[1]), "+f"(d[2]), "+f"(d[3])
        : "r"(a[0]), "r"(a[1]), "r"(a[2]), "r"(a[3]), "r"(b[0]), "r"(b[1]));
}

// dynamic smem: 3 stages x (A 16KB + B 16KB) = 96KB @0, s_part 1KB @98304
static constexpr int STAGE_BYTES = 32768;           // A 16KB + B 16KB
static constexpr int SMEM_SZ = 3 * STAGE_BYTES + 1024;

// ---------------------------------------------------------------------------
// HMMA bf16 GEMM: D[m][n] = sum_k A[m][k]*B[n][k] (both K-major).
// CTA 128x128, k-tile 64, XOR-swizzled smem, 3-stage cp.async pipeline,
// ONE __syncthreads per k-tile. 8 warps (4m x 2n), warptile 32x64.
// EPI: 1 = +bias[m], store bf16
//      2 = (gamma*invS[n])*acc + X[m][n], store fp32
//      3 = exp(acc) -> bf16 store; per-CTA row sums -> spart
// ---------------------------------------------------------------------------
template <int EPI>
__global__ __launch_bounds__(256) void hgemm(
    const __nv_bfloat16* __restrict__ Aall,
    const __nv_bfloat16* __restrict__ Ball,
    void* __restrict__ Cout,
    int K, int ldC,
    long long sA, long long sB, long long sC,
    const float* __restrict__ bias,
    const float* __restrict__ gptr,
    const float* __restrict__ Xall, long long sX,
    float* __restrict__ spart,
    const float* __restrict__ invS)
{
    extern __shared__ __align__(1024) char sm[];
    const uint32_t smA = smem_u32(sm);                 // stage s: smA + s*32768
    const uint32_t smB = smA + 16384;                  //          smB + s*32768
    float* s_part = (float*)(sm + 3 * STAGE_BYTES);

    const int t = threadIdx.x, lane = t & 31, wid = t >> 5;
    const int bz = blockIdx.z;
    const int m0 = blockIdx.y * 128, n0 = blockIdx.x * 128;
    const int wm = wid & 3, wn = wid >> 2;

    const __nv_bfloat16* A = Aall + (size_t)bz * sA + (size_t)m0 * K;
    const __nv_bfloat16* B = Ball + (size_t)bz * sB + (size_t)n0 * K;

    // loader: thread t -> row t>>1, chunks (t&1)*4 .. +3 (16B each, 8 bf16)
    const int lrow = t >> 1;
    const int lc0  = (t & 1) * 4;
    const int lswz = lrow & 7;
    const __nv_bfloat16* Ar = A + (size_t)lrow * K;
    const __nv_bfloat16* Br = B + (size_t)lrow * K;
    const uint32_t dA0 = smA + lrow * 128;
    const uint32_t dB0 = smB + lrow * 128;

    float acc[2][8][4];
#pragma unroll
    for (int i = 0; i < 2; i++)
#pragma unroll
        for (int j = 0; j < 8; j++)
#pragma unroll
            for (int q = 0; q < 4; q++) acc[i][j][q] = 0.f;

#define LOAD_TILE(stg, k0)                                                   \
    do {                                                                     \
        _Pragma("unroll")                                                    \
        for (int j = 0; j < 4; j++) {                                        \
            int c = lc0 + j;                                                 \
            uint32_t ph = (uint32_t)((c ^ lswz) << 4);                       \
            cp16u(dA0 + (stg) * STAGE_BYTES + ph, Ar + (k0) + c * 8);        \
            cp16u(dB0 + (stg) * STAGE_BYTES + ph, Br + (k0) + c * 8);        \
        }                                                                    \
        asm volatile("cp.async.commit_group;");                              \
    } while (0)

    const int nk = K / 64;
    LOAD_TILE(0, 0);
    if (nk > 1) { LOAD_TILE(1, 64); }
    else        { asm volatile("cp.async.commit_group;"); }

    const int a_r = lane & 15;
    const int a_ch = lane >> 4;         // 0/1
    const int b_r = ((lane >> 4) << 3) + (lane & 7);
    const int b_ch = (lane >> 3) & 1;   // 0/1

    int buf = 0;
    for (int kt = 0; kt < nk; kt++) {
        asm volatile("cp.async.wait_group 1;");
        __syncthreads();

        // prefetch stage kt+2 (slot reused from compute of kt-1, safe post-sync)
        const int nxt = kt + 2;
        if (nxt < nk) {
            const int slot = (buf + 2 >= 3) ? buf - 1 : buf + 2;
            LOAD_TILE(slot, nxt * 64);
        } else {
            asm volatile("cp.async.commit_group;");
        }

        const uint32_t bA = smA + buf * STAGE_BYTES;
        const uint32_t bB = smB + buf * STAGE_BYTES;
#pragma unroll
        for (int s = 0; s < 4; s++) {
            uint32_t af[2][4];
#pragma unroll
            for (int mt = 0; mt < 2; mt++) {
                int r = wm * 32 + mt * 16 + a_r;
                int c = s * 2 + a_ch;
                ldsm_x4(af[mt], bA + r * 128 + ((c ^ (r & 7)) << 4));
            }
            uint32_t bf_[4][4];
#pragma unroll
            for (int ng = 0; ng < 4; ng++) {
                int r = wn * 64 + ng * 16 + b_r;
                int c = s * 2 + b_ch;
                ldsm_x4(bf_[ng], bB + r * 128 + ((c ^ (r & 7)) << 4));
            }
#pragma unroll
            for (int mt = 0; mt < 2; mt++)
#pragma unroll
                for (int nt = 0; nt < 8; nt++)
                    mma16816(acc[mt][nt], af[mt], &bf_[nt >> 1][(nt & 1) * 2]);
        }
        buf = (buf + 1 == 3) ? 0 : buf + 1;
    }
#undef LOAD_TILE

    // ---------------- epilogue ----------------
    const int cr = lane >> 2;
    const int cc = (lane & 3) * 2;

    if (EPI == 1) {
        __nv_bfloat16* C = (__nv_bfloat16*)Cout + (size_t)bz * sC;
#pragma unroll
        for (int mt = 0; mt < 2; mt++) {
            float bv0 = bias[m0 + wm * 32 + mt * 16 + cr];
            float bv1 = bias[m0 + wm * 32 + mt * 16 + cr + 8];
#pragma unroll
            for (int nt = 0; nt < 8; nt++) {
                int col = n0 + wn * 64 + nt * 8 + cc;
#pragma unroll
                for (int h = 0; h < 2; h++) {
                    int row = m0 + wm * 32 + mt * 16 + cr + h * 8;
                    float bv = h ? bv1 : bv0;
                    __nv_bfloat162 o;
                    o.x = __float2bfloat16(acc[mt][nt][h * 2] + bv);
                    o.y = __float2bfloat16(acc[mt][nt][h * 2 + 1] + bv);
                    *(__nv_bfloat162*)(C + (size_t)row * ldC + col) = o;
                }
            }
        }
    } else if (EPI == 2) {
        const float g = gptr[0];
        const float* X = Xall + (size_t)bz * sX;
        const float* iS = invS + (size_t)bz * Ll;
        float* C = (float*)Cout + (size_t)bz * sC;
#pragma unroll
        for (int nt = 0; nt < 8; nt++) {
            int col = n0 + wn * 64 + nt * 8 + cc;
            float gi0 = g * iS[col];
            float gi1 = g * iS[col + 1];
#pragma unroll
            for (int mt = 0; mt < 2; mt++)
#pragma unroll
                for (int h = 0; h < 2; h++) {
                    int row = m0 + wm * 32 + mt * 16 + cr + h * 8;
                    float2 xv = *(const float2*)(X + (size_t)row * ldC + col);
                    float2 o;
                    o.x = fmaf(gi0, acc[mt][nt][h * 2], xv.x);
                    o.y = fmaf(gi1, acc[mt][nt][h * 2 + 1], xv.y);
                    *(float2*)(C + (size_t)row * ldC + col) = o;
                }
        }
    } else {
        // EPI 3: exp + bf16 store + row-sum partials
        __nv_bfloat16* C = (__nv_bfloat16*)Cout + (size_t)bz * sC;
        float rs[2][2] = {{0.f, 0.f}, {0.f, 0.f}};
#pragma unroll
        for (int mt = 0; mt < 2; mt++)
#pragma unroll
            for (int nt = 0; nt < 8; nt++) {
                int col = n0 + wn * 64 + nt * 8 + cc;
#pragma unroll
                for (int h = 0; h < 2; h++) {
                    int row = m0 + wm * 32 + mt * 16 + cr + h * 8;
                    float e0 = __expf(acc[mt][nt][h * 2]);
                    float e1 = __expf(acc[mt][nt][h * 2 + 1]);
                    __nv_bfloat162 o;
                    o.x = __float2bfloat16(e0);
                    o.y = __float2bfloat16(e1);
                    *(__nv_bfloat162*)(C + (size_t)row * ldC + col) = o;
                    rs[mt][h] += e0 + e1;
                }
            }
#pragma unroll
        for (int mt = 0; mt < 2; mt++)
#pragma unroll
            for (int h = 0; h < 2; h++) {
                float v = rs[mt][h];
                v += __shfl_xor_sync(0xffffffffu, v, 1);
                v += __shfl_xor_sync(0xffffffffu, v, 2);
                rs[mt][h] = v;
            }
        __syncthreads();   // reuse smem for partial sums after pipeline drained
        if ((lane & 3) == 0) {
#pragma unroll
            for (int mt = 0; mt < 2; mt++)
#pragma unroll
                for (int h = 0; h < 2; h++)
                    s_part[wn * 128 + wm * 32 + mt * 16 + cr + h * 8] = rs[mt][h];
        }
        __syncthreads();
        if (t < 128) {
            size_t idx = ((size_t)bz * 32 + blockIdx.x) * Ll + m0 + t;
            spart[idx] = s_part[t] + s_part[128 + t];
        }
    }
}

// ---------------------------------------------------------------------------
// reduce partials -> 1/rowsum
// ---------------------------------------------------------------------------
__global__ __launch_bounds__(256) void reduce_s_kernel()
{
    int idx = blockIdx.x * 256 + threadIdx.x;     // 0 .. B*L-1
    int b = idx >> 12, m = idx & 4095;
    float s = 0.f;
#pragma unroll 8
    for (int nt = 0; nt < 32; nt++)
        s += g_spart[((size_t)b * 32 + nt) * Ll + m];
    g_invs[idx] = 1.0f / s;
}

// ---------------------------------------------------------------------------
// q/k projection -> split bf16 layouts (fp32 math)
// ---------------------------------------------------------------------------
__global__ __launch_bounds__(256) void proj_qk_kernel(
    const float* __restrict__ x,
    const float* __restrict__ Wq, const float* __restrict__ bq,
    const float* __restrict__ Wk, const float* __restrict__ bk)
{
    const int b  = blockIdx.y;
    const int l0 = blockIdx.x * 64;

    __shared__ float xs[64][64];
    __shared__ float wqs[64][65];
    __shared__ float wks[64][65];

    const int t  = threadIdx.x;
    const int tx = t & 63;
    const int ty = t >> 6;

    float accq[16], acck[16];
#pragma unroll
    for (int i = 0; i < 16; i++) { accq[i] = 0.f; acck[i] = 0.f; }

    const float* xb = x + (size_t)b * Cc * Ll;
    const int row  = t >> 2;
    const int off0 = (t & 3) * 16;

    for (int cc = 0; cc < Cc; cc += 64) {
#pragma unroll
        for (int j = 0; j < 16; j += 4) {
            float4 v = *(const float4*)(xb + (size_t)(cc + row) * Ll + l0 + off0 + j);
            *(float4*)&xs[row][off0 + j] = v;
        }
#pragma unroll
        for (int j = 0; j < 16; j += 4) {
            float4 vq = *(const float4*)(Wq + row * Cc + cc + off0 + j);
            wqs[off0 + j + 0][row] = vq.x;
            wqs[off0 + j + 1][row] = vq.y;
            wqs[off0 + j + 2][row] = vq.z;
            wqs[off0 + j + 3][row] = vq.w;
            float4 vk = *(const float4*)(Wk + row * Cc + cc + off0 + j);
            wks[off0 + j + 0][row] = vk.x;
            wks[off0 + j + 1][row] = vk.y;
            wks[off0 + j + 2][row] = vk.z;
            wks[off0 + j + 3][row] = vk.w;
        }
        __syncthreads();
#pragma unroll 4
        for (int ci = 0; ci < 64; ci++) {
            float wq = wqs[ci][tx];
            float wk = wks[ci][tx];
#pragma unroll
            for (int i = 0; i < 16; i++) {
                float xv = xs[ci][ty * 16 + i];
                accq[i] = fmaf(wq, xv, accq[i]);
                acck[i] = fmaf(wk, xv, acck[i]);
            }
        }
        __syncthreads();
    }

    const float bqv = bq[tx];
    const float bkv = bk[tx];
#pragma unroll
    for (int i = 0; i < 16; i++) {
        int l = l0 + ty * 16 + i;
        size_t base = ((size_t)b * Ll + l) * 192;
        float qv = accq[i] + bqv;
        __nv_bfloat16 qh = __float2bfloat16(qv);
        __nv_bfloat16 ql = __float2bfloat16(qv - __bfloat162float(qh));
        g_qa[base + tx]       = qh;
        g_qa[base + 64 + tx]  = qh;
        g_qa[base + 128 + tx] = ql;
        float kv = acck[i] + bkv;
        __nv_bfloat16 kh = __float2bfloat16(kv);
        __nv_bfloat16 kl = __float2bfloat16(kv - __bfloat162float(kh));
        g_kb[base + tx]       = kh;
        g_kb[base + 64 + tx]  = kl;
        g_kb[base + 128 + tx] = kh;
    }
}

// ---------------------------------------------------------------------------
__global__ __launch_bounds__(256) void transpose_x_kernel(const float* __restrict__ x)
{
    __shared__ float tile[32][33];
    const int b  = blockIdx.z;
    const int c0 = blockIdx.y * 32;
    const int l0 = blockIdx.x * 32;
    const int tx = threadIdx.x, ty = threadIdx.y;

    const float* xb = x + ((size_t)b * Cc + c0) * Ll + l0;
#pragma unroll
    for (int r = 0; r < 4; r++)
        tile[ty + r * 8][tx] = xb[(size_t)(ty + r * 8) * Ll + tx];
    __syncthreads();

    __nv_bfloat16* o = g_xT + (size_t)b * Ll * Cc;
#pragma unroll
    for (int r = 0; r < 4; r++) {
        int l = l0 + ty + r * 8;
        o[(size_t)l * Cc + c0 + tx] = __float2bfloat16(tile[tx][ty + r * 8]);
    }
}

__global__ __launch_bounds__(256) void conv_wv_kernel(const float* __restrict__ Wv)
{
    int idx = blockIdx.x * 256 + threadIdx.x;
    g_wv[idx] = __float2bfloat16(Wv[idx]);
}

// ---------------------------------------------------------------------------
extern "C" void kernel_launch(void* const* d_in, const int* in_sizes, int n_in,
                              void* d_out, int out_size)
{
    const float* x     = (const float*)d_in[0];
    const float* Wq    = (const float*)d_in[1];
    const float* bq    = (const float*)d_in[2];
    const float* Wk    = (const float*)d_in[3];
    const float* bk    = (const float*)d_in[4];
    const float* Wv    = (const float*)d_in[5];
    const float* bv    = (const float*)d_in[6];
    const float* gamma = (const float*)d_in[7];
    float* out = (float*)d_out;

    __nv_bfloat16 *qa, *kb, *xT, *wv, *v, *p;
    float *spart, *invs;
    cudaGetSymbolAddress((void**)&qa, g_qa);
    cudaGetSymbolAddress((void**)&kb, g_kb);
    cudaGetSymbolAddress((void**)&xT, g_xT);
    cudaGetSymbolAddress((void**)&wv, g_wv);
    cudaGetSymbolAddress((void**)&v,  g_v);
    cudaGetSymbolAddress((void**)&p,  g_p);
    cudaGetSymbolAddress((void**)&spart, g_spart);
    cudaGetSymbolAddress((void**)&invs,  g_invs);

    cudaFuncSetAttribute(hgemm<1>, cudaFuncAttributeMaxDynamicSharedMemorySize, SMEM_SZ);
    cudaFuncSetAttribute(hgemm<2>, cudaFuncAttributeMaxDynamicSharedMemorySize, SMEM_SZ);
    cudaFuncSetAttribute(hgemm<3>, cudaFuncAttributeMaxDynamicSharedMemorySize, SMEM_SZ);

    // 1) prologue conversions
    proj_qk_kernel<<<dim3(Ll / 64, Bb), 256>>>(x, Wq, bq, Wk, bk);
    transpose_x_kernel<<<dim3(Ll / 32, Cc / 32, Bb), dim3(32, 8)>>>(x);
    conv_wv_kernel<<<(Cc * Cc) / 256, 256>>>(Wv);

    // 2) v = Wv @ x + bv  -> bf16 [C, L]
    hgemm<1><<<dim3(Ll / 128, Cc / 128, Bb), 256, SMEM_SZ>>>(
        wv, xT, v, Cc, Ll,
        0LL, (long long)Ll * Cc, (long long)Cc * Ll,
        bv, nullptr, nullptr, 0LL, nullptr, nullptr);

    // 3) p = exp(q @ k^T)  (K=192 split) -> bf16 [L, L] + row-sum partials
    hgemm<3><<<dim3(Ll / 128, Ll / 128, Bb), 256, SMEM_SZ>>>(
        qa, kb, p, 192, Ll,
        (long long)Ll * 192, (long long)Ll * 192, (long long)Ll * Ll,
        nullptr, nullptr, nullptr, 0LL, spart, nullptr);

    // 4) invS = 1 / rowsum
    reduce_s_kernel<<<(Bb * Ll) / 256, 256>>>();

    // 5) out = (gamma*invS[i]) * (v @ p^T) + x  -> fp32 [C, L]
    hgemm<2><<<dim3(Ll / 128, Cc / 128, Bb), 256, SMEM_SZ>>>(
        v, p, out, Ll, Ll,
        (long long)Cc * Ll, (long long)Ll * Ll, (long long)Cc * Ll,
        nullptr, gamma, x, (long long)Cc * Ll, nullptr, invs);
}